// round 5
// baseline (speedup 1.0000x reference)
#include <cuda_runtime.h>
#include <cuda_bf16.h>
#include <math.h>
#include <stdint.h>

#define D 128
#define MAXN 50176   // 50000 padded up to multiple of 128
#define MAXE 602112

__device__ float g_Q[MAXN * D];
__device__ float g_K[MAXN * D];
__device__ float g_V[MAXN * D];
__device__ float g_agg[MAXN * D];

__device__ int g_cnt[MAXN];
__device__ int g_rowptr[MAXN + 1];
__device__ int g_cursor[MAXN];
__device__ int g_ssrc[MAXE];

// smem tile stride (floats) with padding for conflict-free fragment loads
#define LDT 132
#define TILE_FLOATS (128 * LDT)
#define QKV_SMEM (3 * TILE_FLOATS * 4)   // A + 2x B buffers = 202752 B
#define OPJ_SMEM (2 * TILE_FLOATS * 4)   // A + B = 135168 B

// ---------------------------------------------------------------------------
// helpers
// ---------------------------------------------------------------------------
__device__ __forceinline__ uint32_t f2tf32(float f) {
    uint32_t u;
    asm("cvt.rna.tf32.f32 %0, %1;" : "=r"(u) : "f"(f));
    return u;
}

__device__ __forceinline__ void mma_tf32(float d[4], const uint32_t a[4], const uint32_t b[2]) {
    asm volatile(
        "mma.sync.aligned.m16n8k8.row.col.f32.tf32.tf32.f32 "
        "{%0,%1,%2,%3}, {%4,%5,%6,%7}, {%8,%9}, {%0,%1,%2,%3};"
        : "+f"(d[0]), "+f"(d[1]), "+f"(d[2]), "+f"(d[3])
        : "r"(a[0]), "r"(a[1]), "r"(a[2]), "r"(a[3]), "r"(b[0]), "r"(b[1]));
}

// load one 128x128 fp32 tile -> tf32 smem tile (512 threads, 8 float4 each)
__device__ __forceinline__ void load_tile(const float* __restrict__ src,
                                          uint32_t* __restrict__ Tu,
                                          int m0, int N) {
    const int tid = threadIdx.x;
#pragma unroll
    for (int i = 0; i < 8; ++i) {
        int idx = tid + i * 512;          // 0..4095
        int m = idx >> 5;                 // row 0..127
        int c = idx & 31;                 // float4 col 0..31
        int gm = m0 + m;
        float4 f = (gm < N) ? *(const float4*)(src + (size_t)gm * D + c * 4)
                            : make_float4(0.f, 0.f, 0.f, 0.f);
        uint4 u = make_uint4(f2tf32(f.x), f2tf32(f.y), f2tf32(f.z), f2tf32(f.w));
        *(uint4*)(Tu + m * LDT + c * 4) = u;
    }
}

// MMA phase: warp computes its 32x32 tile from As x Bs.
__device__ __forceinline__ void mma_phase(const uint32_t* __restrict__ Au,
                                          const uint32_t* __restrict__ Bu,
                                          float acc[2][4][4]) {
    const int lane = threadIdx.x & 31;
    const int warp = threadIdx.x >> 5;
    const int mb = (warp & 3) * 32;
    const int nb = (warp >> 2) * 32;
    const int lq = lane >> 2;
    const int lr = lane & 3;

#pragma unroll
    for (int i = 0; i < 2; ++i)
#pragma unroll
        for (int j = 0; j < 4; ++j)
#pragma unroll
            for (int t = 0; t < 4; ++t) acc[i][j][t] = 0.0f;

#pragma unroll
    for (int k0 = 0; k0 < 16; ++k0) {
        const int k = k0 * 8 + lr;
        uint32_t a[2][4], b[4][2];
#pragma unroll
        for (int i = 0; i < 2; ++i) {
            int r0 = mb + i * 16 + lq;
            a[i][0] = Au[r0 * LDT + k];
            a[i][1] = Au[(r0 + 8) * LDT + k];
            a[i][2] = Au[r0 * LDT + k + 4];
            a[i][3] = Au[(r0 + 8) * LDT + k + 4];
        }
#pragma unroll
        for (int j = 0; j < 4; ++j) {
            int c0 = nb + j * 8 + lq;
            b[j][0] = Bu[c0 * LDT + k];
            b[j][1] = Bu[c0 * LDT + k + 4];
        }
#pragma unroll
        for (int i = 0; i < 2; ++i)
#pragma unroll
            for (int j = 0; j < 4; ++j)
                mma_tf32(acc[i][j], a[i], b[j]);
    }
}

// ---------------------------------------------------------------------------
// Fused QKV kernel
// ---------------------------------------------------------------------------
__global__ void __launch_bounds__(512, 1)
qkv_kernel(const float* __restrict__ X,
           const float* __restrict__ Wq, const float* __restrict__ Wk,
           const float* __restrict__ Wv,
           float* __restrict__ Q, float* __restrict__ K, float* __restrict__ V,
           int N)
{
    extern __shared__ float smem[];
    uint32_t* Au = (uint32_t*)smem;
    uint32_t* Bu[2] = {(uint32_t*)(smem + TILE_FLOATS),
                       (uint32_t*)(smem + 2 * TILE_FLOATS)};

    const float* Wlist[3] = {Wq, Wk, Wv};
    float*       Olist[3] = {Q, K, V};
    const int m0 = blockIdx.x * 128;

    load_tile(X, Au, m0, N);
    load_tile(Wlist[0], Bu[0], 0, 128);
    __syncthreads();

    const int lane = threadIdx.x & 31;
    const int warp = threadIdx.x >> 5;
    const int mb = (warp & 3) * 32;
    const int nb = (warp >> 2) * 32;
    const int lq = lane >> 2;
    const int lr = lane & 3;

#pragma unroll
    for (int w = 0; w < 3; ++w) {
        if (w < 2) load_tile(Wlist[w + 1], Bu[(w + 1) & 1], 0, 128);

        float acc[2][4][4];
        mma_phase(Au, Bu[w & 1], acc);

        float* O = Olist[w];
#pragma unroll
        for (int i = 0; i < 2; ++i) {
            int row = m0 + mb + i * 16 + lq;
#pragma unroll
            for (int j = 0; j < 4; ++j) {
                int col = nb + j * 8 + lr * 2;
                if (row < N)
                    *(float2*)(O + (size_t)row * D + col) = make_float2(acc[i][j][0], acc[i][j][1]);
                if (row + 8 < N)
                    *(float2*)(O + (size_t)(row + 8) * D + col) = make_float2(acc[i][j][2], acc[i][j][3]);
            }
        }
        __syncthreads();
    }
}

// ---------------------------------------------------------------------------
// O-proj + bias + residual + LayerNorm fused
// ---------------------------------------------------------------------------
__global__ void __launch_bounds__(512, 1)
oproj_ln_kernel(const float* __restrict__ AGG, const float* __restrict__ Wo,
                const float* __restrict__ X,
                const float* __restrict__ bo, const float* __restrict__ gamma,
                const float* __restrict__ beta,
                float* __restrict__ out, int N)
{
    extern __shared__ float smem[];
    uint32_t* Au = (uint32_t*)smem;
    uint32_t* Bu = (uint32_t*)(smem + TILE_FLOATS);
    float* Hs = smem;
    __shared__ float P[384];

    const int tid = threadIdx.x;
    if (tid < 128)       P[tid]       = bo[tid];
    else if (tid < 256)  P[tid]       = gamma[tid - 128];
    else if (tid < 384)  P[tid]       = beta[tid - 256];

    const int m0 = blockIdx.x * 128;

    load_tile(AGG, Au, m0, N);
    load_tile(Wo, Bu, 0, 128);
    __syncthreads();

    float acc[2][4][4];
    mma_phase(Au, Bu, acc);
    __syncthreads();

    const int lane = tid & 31;
    const int warp = tid >> 5;
    const int mb = (warp & 3) * 32;
    const int nb = (warp >> 2) * 32;
    const int lq = lane >> 2;
    const int lr = lane & 3;

#pragma unroll
    for (int i = 0; i < 2; ++i) {
        int r = mb + i * 16 + lq;
#pragma unroll
        for (int j = 0; j < 4; ++j) {
            int c = nb + j * 8 + lr * 2;
            *(float2*)(Hs + r * LDT + c)       = make_float2(acc[i][j][0], acc[i][j][1]);
            *(float2*)(Hs + (r + 8) * LDT + c) = make_float2(acc[i][j][2], acc[i][j][3]);
        }
    }
    __syncthreads();

#pragma unroll
    for (int p = 0; p < 8; ++p) {
        int r = warp * 8 + p;
        int grow = m0 + r;
        if (grow >= N) continue;

        float4 h = *(float4*)(Hs + r * LDT + lane * 4);
        float4 xb = *(const float4*)(X + (size_t)grow * D + lane * 4);
        float4 bb = *(const float4*)(P + lane * 4);
        h.x += xb.x + bb.x; h.y += xb.y + bb.y;
        h.z += xb.z + bb.z; h.w += xb.w + bb.w;

        float s  = h.x + h.y + h.z + h.w;
        float s2 = h.x * h.x + h.y * h.y + h.z * h.z + h.w * h.w;
#pragma unroll
        for (int o = 16; o; o >>= 1) {
            s  += __shfl_xor_sync(0xffffffffu, s,  o);
            s2 += __shfl_xor_sync(0xffffffffu, s2, o);
        }
        float mu  = s * (1.0f / 128.0f);
        float var = s2 * (1.0f / 128.0f) - mu * mu;
        float rv  = rsqrtf(var + 1e-5f);

        float4 gm = *(const float4*)(P + 128 + lane * 4);
        float4 bt = *(const float4*)(P + 256 + lane * 4);
        float4 o;
        o.x = (h.x - mu) * rv * gm.x + bt.x;
        o.y = (h.y - mu) * rv * gm.y + bt.y;
        o.z = (h.z - mu) * rv * gm.z + bt.z;
        o.w = (h.w - mu) * rv * gm.w + bt.w;
        *(float4*)(out + (size_t)grow * D + lane * 4) = o;
    }
}

// ---------------------------------------------------------------------------
// CSR build: histogram -> scan -> scatter
// ---------------------------------------------------------------------------
__global__ void zero_int_kernel(int* __restrict__ p, int n) {
    int i = blockIdx.x * blockDim.x + threadIdx.x;
    if (i < n) p[i] = 0;
}

__global__ void hist_kernel(const int* __restrict__ ei, int* __restrict__ cnt, int E) {
    int e = blockIdx.x * blockDim.x + threadIdx.x;
    if (e < E) atomicAdd(&cnt[ei[E + e]], 1);
}

__global__ void __launch_bounds__(1024, 1)
scan_kernel(const int* __restrict__ cnt, int* __restrict__ rowptr,
            int* __restrict__ cursor, int N)
{
    __shared__ int part[1024];
    const int t = threadIdx.x;
    const int chunk = (N + 1023) / 1024;
    const int b = t * chunk;
    const int e = min(b + chunk, N);

    int s = 0;
    for (int i = b; i < e; ++i) s += cnt[i];
    part[t] = s;
    __syncthreads();

    // Hillis-Steele inclusive scan
    for (int o = 1; o < 1024; o <<= 1) {
        int v = (t >= o) ? part[t - o] : 0;
        __syncthreads();
        part[t] += v;
        __syncthreads();
    }

    int run = part[t] - s;   // exclusive prefix of this thread's chunk
    for (int i = b; i < e; ++i) {
        rowptr[i] = run;
        cursor[i] = run;
        run += cnt[i];
    }
    if (t == 1023) rowptr[N] = part[1023];
}

__global__ void scatter_kernel(const int* __restrict__ ei, int* __restrict__ cursor,
                               int* __restrict__ ssrc, int E)
{
    int e = blockIdx.x * blockDim.x + threadIdx.x;
    if (e < E) {
        int dst = ei[E + e];
        int p = atomicAdd(&cursor[dst], 1);
        ssrc[p] = ei[e];
    }
}

// ---------------------------------------------------------------------------
// Aggregation: one warp per dst node, no atomics.
// agg[dst] = sum_{e in group(dst)} sigmoid(dot(Q[dst],K[src_e])/sqrt(D)) * V[src_e]
// ---------------------------------------------------------------------------
__global__ void agg_kernel(const int* __restrict__ ssrc,
                           const int* __restrict__ rowptr,
                           const float* __restrict__ Q,
                           const float* __restrict__ K,
                           const float* __restrict__ V,
                           float* __restrict__ agg, int N)
{
    int node = (blockIdx.x * blockDim.x + threadIdx.x) >> 5;
    int lane = threadIdx.x & 31;
    if (node >= N) return;

    const int beg = rowptr[node];
    const int end = rowptr[node + 1];

    const float4 q = *(const float4*)&Q[(size_t)node * D + lane * 4];
    float4 acc = make_float4(0.f, 0.f, 0.f, 0.f);

    int e = beg;
    for (; e + 2 <= end; e += 2) {
        int s0 = ssrc[e];
        int s1 = ssrc[e + 1];
        const float4 k0 = *(const float4*)&K[(size_t)s0 * D + lane * 4];
        const float4 k1 = *(const float4*)&K[(size_t)s1 * D + lane * 4];
        const float4 v0 = *(const float4*)&V[(size_t)s0 * D + lane * 4];
        const float4 v1 = *(const float4*)&V[(size_t)s1 * D + lane * 4];

        float d0 = q.x * k0.x + q.y * k0.y + q.z * k0.z + q.w * k0.w;
        float d1 = q.x * k1.x + q.y * k1.y + q.z * k1.z + q.w * k1.w;
#pragma unroll
        for (int o = 16; o; o >>= 1) {
            d0 += __shfl_xor_sync(0xffffffffu, d0, o);
            d1 += __shfl_xor_sync(0xffffffffu, d1, o);
        }
        float w0 = 1.0f / (1.0f + __expf(-d0 * 0.08838834764831845f));
        float w1 = 1.0f / (1.0f + __expf(-d1 * 0.08838834764831845f));
        acc.x += w0 * v0.x + w1 * v1.x;
        acc.y += w0 * v0.y + w1 * v1.y;
        acc.z += w0 * v0.z + w1 * v1.z;
        acc.w += w0 * v0.w + w1 * v1.w;
    }
    if (e < end) {
        int s0 = ssrc[e];
        const float4 k0 = *(const float4*)&K[(size_t)s0 * D + lane * 4];
        const float4 v0 = *(const float4*)&V[(size_t)s0 * D + lane * 4];
        float d0 = q.x * k0.x + q.y * k0.y + q.z * k0.z + q.w * k0.w;
#pragma unroll
        for (int o = 16; o; o >>= 1) d0 += __shfl_xor_sync(0xffffffffu, d0, o);
        float w0 = 1.0f / (1.0f + __expf(-d0 * 0.08838834764831845f));
        acc.x += w0 * v0.x; acc.y += w0 * v0.y;
        acc.z += w0 * v0.z; acc.w += w0 * v0.w;
    }

    *(float4*)&agg[(size_t)node * D + lane * 4] = acc;
}

// ---------------------------------------------------------------------------
// launch
// ---------------------------------------------------------------------------
extern "C" void kernel_launch(void* const* d_in, const int* in_sizes, int n_in,
                              void* d_out, int out_size)
{
    const float* x     = (const float*)d_in[0];
    const int*   ei    = (const int*)  d_in[1];
    const float* Wq    = (const float*)d_in[2];
    const float* Wk    = (const float*)d_in[3];
    const float* Wv    = (const float*)d_in[4];
    const float* Wo    = (const float*)d_in[5];
    const float* bo    = (const float*)d_in[6];
    const float* gamma = (const float*)d_in[7];
    const float* beta  = (const float*)d_in[8];
    float*       out   = (float*)d_out;

    const int N = in_sizes[0] / D;
    const int E = in_sizes[1] / 2;

    float *Q, *K, *V, *agg;
    int *cnt, *rowptr, *cursor, *ssrc;
    cudaGetSymbolAddress((void**)&Q,      g_Q);
    cudaGetSymbolAddress((void**)&K,      g_K);
    cudaGetSymbolAddress((void**)&V,      g_V);
    cudaGetSymbolAddress((void**)&agg,    g_agg);
    cudaGetSymbolAddress((void**)&cnt,    g_cnt);
    cudaGetSymbolAddress((void**)&rowptr, g_rowptr);
    cudaGetSymbolAddress((void**)&cursor, g_cursor);
    cudaGetSymbolAddress((void**)&ssrc,   g_ssrc);

    cudaFuncSetAttribute(qkv_kernel, cudaFuncAttributeMaxDynamicSharedMemorySize, QKV_SMEM);
    cudaFuncSetAttribute(oproj_ln_kernel, cudaFuncAttributeMaxDynamicSharedMemorySize, OPJ_SMEM);

    const int mb = (N + 127) / 128;

    // CSR build
    zero_int_kernel<<<(N + 255) / 256, 256>>>(cnt, N);
    hist_kernel<<<(E + 255) / 256, 256>>>(ei, cnt, E);
    scan_kernel<<<1, 1024>>>(cnt, rowptr, cursor, N);
    scatter_kernel<<<(E + 255) / 256, 256>>>(ei, cursor, ssrc, E);

    // projections
    qkv_kernel<<<mb, 512, QKV_SMEM>>>(x, Wq, Wk, Wv, Q, K, V, N);

    // aggregation (no atomics)
    agg_kernel<<<(N + 7) / 8, 256>>>(ssrc, rowptr, Q, K, V, agg, N);

    // output projection + LN
    oproj_ln_kernel<<<mb, 512, OPJ_SMEM>>>(agg, Wo, x, bo, gamma, beta, out, N);
}